// round 1
// baseline (speedup 1.0000x reference)
#include <cuda_runtime.h>
#include <cstdint>

// Problem geometry
#define HW 1024      // 32x32 spatial, contiguous in NCHW
#define N_IMG 32

// GEMM tiling
#define BM 128
#define BN 128
#define BK 16
#define LDA 20       // BK + 4 pad (conflict-free A frag loads)
#define LDB 136      // BN + 8 pad (conflict-free B frag loads)

// Scratch for intermediates (allocation-free rule: __device__ globals)
__device__ float g_out1[N_IMG * 256 * HW];
__device__ float g_out2[N_IMG * 256 * HW];

__device__ __forceinline__ uint32_t f2tf32(float x) {
    uint32_t r;
    asm("cvt.rna.tf32.f32 %0, %1;" : "=r"(r) : "f"(x));
    return r;
}

__device__ __forceinline__ void mma_tf32(float* d, const uint32_t* a, const uint32_t* b) {
    asm volatile(
        "mma.sync.aligned.m16n8k8.row.col.f32.tf32.tf32.f32 "
        "{%0,%1,%2,%3}, {%4,%5,%6,%7}, {%8,%9}, {%0,%1,%2,%3};\n"
        : "+f"(d[0]), "+f"(d[1]), "+f"(d[2]), "+f"(d[3])
        : "r"(a[0]), "r"(a[1]), "r"(a[2]), "r"(a[3]),
          "r"(b[0]), "r"(b[1]));
}

// C[n] (M x 1024) = A (M x K) @ B[n] (K x 1024), epilogue: affine+ReLU (+residual)
// CONV3 = true: implicit 3x3 conv, K = 9*b_ch, B indexed with spatial shift + border mask
template<bool CONV3, bool RESID>
__global__ __launch_bounds__(256, 2)
void gemm_fused(const float* __restrict__ A,
                const float* __restrict__ B,
                float* __restrict__ C,
                const float* __restrict__ scale,
                const float* __restrict__ bias,
                const float* __restrict__ resid,
                int M, int K, int b_ch)
{
    const int n_img = blockIdx.z;
    const int bm = blockIdx.y;
    const int bn = blockIdx.x;
    const int tid = threadIdx.x;
    const int lane = tid & 31;
    const int warp = tid >> 5;
    const int wm = (warp & 3) << 5;   // warp m offset: 0/32/64/96
    const int wn = (warp >> 2) << 6;  // warp n offset: 0/64
    const int g  = lane >> 2;         // 0..7
    const int tc = lane & 3;          // 0..3

    __shared__ uint32_t As[BM * LDA];
    __shared__ uint32_t Bs[BK * LDB];

    float acc[2][8][4];
    #pragma unroll
    for (int i = 0; i < 2; i++)
        #pragma unroll
        for (int j = 0; j < 8; j++)
            #pragma unroll
            for (int q = 0; q < 4; q++) acc[i][j][q] = 0.f;

    const float* Bimg = B + (size_t)n_img * b_ch * HW;

    for (int k0 = 0; k0 < K; k0 += BK) {
        // ---- A tile: BM x BK (row-major, K-stride) ----
        #pragma unroll
        for (int i = 0; i < 2; i++) {
            int e = tid + i * 256;          // 0..511 float4 slots
            int row = e >> 2;               // 4 float4 per 16-float row
            int c4  = (e & 3) << 2;
            const float4 v = *(const float4*)(A + (size_t)(bm * BM + row) * K + k0 + c4);
            uint32_t* dst = &As[row * LDA + c4];
            dst[0] = f2tf32(v.x); dst[1] = f2tf32(v.y);
            dst[2] = f2tf32(v.z); dst[3] = f2tf32(v.w);
        }
        // ---- B tile: BK x BN ----
        if (!CONV3) {
            #pragma unroll
            for (int i = 0; i < 2; i++) {
                int e = tid + i * 256;
                int row = e >> 5;           // 32 float4 per 128-float row
                int c4  = (e & 31) << 2;
                const float4 v = *(const float4*)(Bimg + (size_t)(k0 + row) * HW + bn * BN + c4);
                uint32_t* dst = &Bs[row * LDB + c4];
                dst[0] = f2tf32(v.x); dst[1] = f2tf32(v.y);
                dst[2] = f2tf32(v.z); dst[3] = f2tf32(v.w);
            }
        } else {
            // implicit 3x3: k -> (ci, kh, kw); spatial shift with zero border
            #pragma unroll
            for (int i = 0; i < 8; i++) {
                int e = tid + i * 256;      // 0..2047
                int row = e >> 7;
                int col = e & 127;
                int k = k0 + row;
                int ci = k / 9;
                int t = k - ci * 9;
                int dh = t / 3 - 1;
                int dw = t - (t / 3) * 3 - 1;
                int j = bn * BN + col;
                int hh = (j >> 5) + dh;
                int ww = (j & 31) + dw;
                float v = 0.f;
                if ((unsigned)hh < 32u && (unsigned)ww < 32u)
                    v = Bimg[ci * HW + (hh << 5) + ww];
                Bs[row * LDB + col] = f2tf32(v);
            }
        }
        __syncthreads();

        // ---- compute: 2 k8 steps, 2x8 mma tiles per warp ----
        #pragma unroll
        for (int kk = 0; kk < BK; kk += 8) {
            uint32_t af[2][4];
            #pragma unroll
            for (int mi = 0; mi < 2; mi++) {
                int r = wm + mi * 16 + g;
                af[mi][0] = As[r * LDA + kk + tc];
                af[mi][1] = As[(r + 8) * LDA + kk + tc];
                af[mi][2] = As[r * LDA + kk + 4 + tc];
                af[mi][3] = As[(r + 8) * LDA + kk + 4 + tc];
            }
            uint32_t bf[8][2];
            #pragma unroll
            for (int ni = 0; ni < 8; ni++) {
                int cix = wn + ni * 8 + g;
                bf[ni][0] = Bs[(kk + tc) * LDB + cix];
                bf[ni][1] = Bs[(kk + 4 + tc) * LDB + cix];
            }
            #pragma unroll
            for (int mi = 0; mi < 2; mi++)
                #pragma unroll
                for (int ni = 0; ni < 8; ni++)
                    mma_tf32(acc[mi][ni], af[mi], bf[ni]);
        }
        __syncthreads();
    }

    // ---- epilogue: affine + (residual) + ReLU ----
    #pragma unroll
    for (int mi = 0; mi < 2; mi++) {
        int r0 = bm * BM + wm + mi * 16 + g;
        int r1 = r0 + 8;
        float s0 = scale[r0], bb0 = bias[r0];
        float s1 = scale[r1], bb1 = bias[r1];
        size_t base0 = ((size_t)(n_img * M + r0)) << 10;
        size_t base1 = ((size_t)(n_img * M + r1)) << 10;
        #pragma unroll
        for (int ni = 0; ni < 8; ni++) {
            int col = bn * BN + wn + ni * 8 + tc * 2;
            float v0 = acc[mi][ni][0] * s0 + bb0;
            float v1 = acc[mi][ni][1] * s0 + bb0;
            float v2 = acc[mi][ni][2] * s1 + bb1;
            float v3 = acc[mi][ni][3] * s1 + bb1;
            if (RESID) {
                v0 += resid[base0 + col];
                v1 += resid[base0 + col + 1];
                v2 += resid[base1 + col];
                v3 += resid[base1 + col + 1];
            }
            C[base0 + col]     = fmaxf(v0, 0.f);
            C[base0 + col + 1] = fmaxf(v1, 0.f);
            C[base1 + col]     = fmaxf(v2, 0.f);
            C[base1 + col + 1] = fmaxf(v3, 0.f);
        }
    }
}

extern "C" void kernel_launch(void* const* d_in, const int* in_sizes, int n_in,
                              void* d_out, int out_size)
{
    const float* x  = (const float*)d_in[0];
    const float* w1 = (const float*)d_in[1];
    const float* w2 = (const float*)d_in[2];
    const float* w3 = (const float*)d_in[3];
    const float* s1 = (const float*)d_in[4];
    const float* b1 = (const float*)d_in[5];
    const float* s2 = (const float*)d_in[6];
    const float* b2 = (const float*)d_in[7];
    const float* s3 = (const float*)d_in[8];
    const float* b3 = (const float*)d_in[9];
    float* out = (float*)d_out;

    float *o1, *o2;
    cudaGetSymbolAddress((void**)&o1, g_out1);
    cudaGetSymbolAddress((void**)&o2, g_out2);

    dim3 blk(256);
    // conv1: 1x1, M=256, K=1024
    gemm_fused<false, false><<<dim3(HW / BN, 256 / BM, N_IMG), blk>>>(
        w1, x, o1, s1, b1, nullptr, 256, 1024, 1024);
    // conv2: 3x3 pad1, M=256, K=2304 (implicit)
    gemm_fused<true, false><<<dim3(HW / BN, 256 / BM, N_IMG), blk>>>(
        w2, o1, o2, s2, b2, nullptr, 256, 2304, 256);
    // conv3: 1x1, M=1024, K=256, + residual + ReLU
    gemm_fused<false, true><<<dim3(HW / BN, 1024 / BM, N_IMG), blk>>>(
        w3, o2, out, s3, b3, x, 1024, 256, 256);
}

// round 3
// speedup vs baseline: 1.1188x; 1.1188x over previous
#include <cuda_runtime.h>
#include <cstdint>

#define HW 1024
#define N_IMG 32
#define SMEMB 98304   // 3 stages x (16KB A + 16KB B)

// ---------------- device scratch ----------------
__device__ float g_xt  [N_IMG * HW * 1024];   // x transposed: [img][sp][ci]
__device__ float g_o1t [N_IMG * HW * 256];    // out1 ch-last
__device__ float g_o2t [N_IMG * HW * 256];    // out2 ch-last
__device__ float g_w1s [256 * 1024];
__device__ float g_w2t [9 * 256 * 256];       // [off][co][ci]
__device__ float g_w3s [1024 * 256];

__device__ __forceinline__ uint32_t f2tf(float x) {
    uint32_t r; asm("cvt.rna.tf32.f32 %0, %1;" : "=r"(r) : "f"(x)); return r;
}
__device__ __forceinline__ float tf(float x) { return __uint_as_float(f2tf(x)); }

__device__ __forceinline__ uint32_t smem_u32(const void* p) {
    uint32_t a;
    asm("{ .reg .u64 t; cvta.to.shared.u64 t, %1; cvt.u32.u64 %0, t; }" : "=r"(a) : "l"(p));
    return a;
}

__device__ __forceinline__ void cpasync(uint32_t s, const void* g, uint32_t srcsz) {
    asm volatile("cp.async.cg.shared.global [%0], [%1], 16, %2;"
                 :: "r"(s), "l"(g), "r"(srcsz) : "memory");
}
__device__ __forceinline__ void cpcommit() {
    asm volatile("cp.async.commit_group;" ::: "memory");
}
template<int N>
__device__ __forceinline__ void cpwait() {
    asm volatile("cp.async.wait_group %0;" :: "n"(N) : "memory");
}

__device__ __forceinline__ void ldsm4(uint32_t* r, uint32_t addr) {
    asm volatile("ldmatrix.sync.aligned.m8n8.x4.shared.b16 {%0,%1,%2,%3}, [%4];"
                 : "=r"(r[0]), "=r"(r[1]), "=r"(r[2]), "=r"(r[3]) : "r"(addr));
}

__device__ __forceinline__ void mma_tf32(float* d, const uint32_t* a, uint32_t b0, uint32_t b1) {
    asm volatile(
        "mma.sync.aligned.m16n8k8.row.col.f32.tf32.tf32.f32 "
        "{%0,%1,%2,%3}, {%4,%5,%6,%7}, {%8,%9}, {%0,%1,%2,%3};\n"
        : "+f"(d[0]), "+f"(d[1]), "+f"(d[2]), "+f"(d[3])
        : "r"(a[0]), "r"(a[1]), "r"(a[2]), "r"(a[3]), "r"(b0), "r"(b1));
}

// ---------------- prep kernels ----------------
__global__ void prep_w(const float* __restrict__ w, const float* __restrict__ s,
                       float* __restrict__ o, int K) {
    int i = blockIdx.x * 256 + threadIdx.x;
    o[i] = tf(w[i] * s[i / K]);
}
__global__ void prep_w2(const float* __restrict__ w2, const float* __restrict__ s2,
                        float* __restrict__ o) {
    int i = blockIdx.x * 256 + threadIdx.x;   // 9*256*256
    int off = i >> 16, rem = i & 65535;
    int co = rem >> 8, ci = rem & 255;
    o[i] = tf(w2[co * 2304 + ci * 9 + off] * s2[co]);
}
// x[img][ch][sp] -> xt[img][sp][ch], rounded to tf32
__global__ void transpose_x(const float* __restrict__ x, float* __restrict__ xt) {
    __shared__ float t[32][33];
    int img = blockIdx.z, ch0 = blockIdx.y * 32, sp0 = blockIdx.x * 32;
    int tx = threadIdx.x, ty = threadIdx.y;
    const float* src = x + ((size_t)img * 1024 + ch0) * HW + sp0;
    #pragma unroll
    for (int r = 0; r < 4; r++) t[ty + 8 * r][tx] = src[(ty + 8 * r) * HW + tx];
    __syncthreads();
    float* dst = xt + ((size_t)img * HW + sp0) * 1024 + ch0;
    #pragma unroll
    for (int r = 0; r < 4; r++) dst[(ty + 8 * r) * 1024 + tx] = tf(t[tx][ty + 8 * r]);
}

// ---------------- main GEMM ----------------
// D[128 co][128 sp] = A[co][k] @ Bt[sp][k]^T, tiles K-contig + XOR-swizzled, LDSM feeds.
// CONV: 1 = conv1 (out ch-last), 2 = conv3x3 (out ch-last), 3 = conv3 (out NCHW + resid)
template<int CONV>
__global__ void __launch_bounds__(256, 2)
btl(const float* __restrict__ A, const float* __restrict__ Bt,
    float* __restrict__ C, const float* __restrict__ bias,
    const float* __restrict__ resid, int M, int Astride, int Kch, int NK)
{
    extern __shared__ char smem[];
    const uint32_t sb = smem_u32(smem);
    const int tid = threadIdx.x;
    const int img = blockIdx.z, bm = blockIdx.y, bn = blockIdx.x;
    const int spbase = bn * 128;
    const float* Bimg = Bt + (size_t)img * HW * Kch;

    // ---- stage issue: 8 x cp.async per thread (A: 64B, B: 64B) ----
    const int irow = tid >> 1;        // 0..127
    const int ihalf = tid & 1;        // 64B half of a 128B row

    auto issue = [&](int s) {
        const int k0 = s * 32;
        const uint32_t bufA = sb + (s % 3) * 32768;
        const uint32_t bufB = bufA + 16384;
        const float* gA;
        const float* gB;
        uint32_t bsz = 16;
        if (CONV == 2) {
            const int off = s >> 3;               // 8 stages (256 ch) per offset
            const int ci0 = k0 & 255;
            gA = A + off * 65536 + (bm * 128 + irow) * 256 + ci0 + ihalf * 16;
            const int dh = off / 3 - 1, dw = off % 3 - 1;
            const int sp = spbase + irow;
            const int hh = (sp >> 5) + dh, ww = (sp & 31) + dw;
            const bool valid = ((unsigned)hh < 32u) & ((unsigned)ww < 32u);
            gB = valid ? (Bimg + (size_t)((hh << 5) + ww) * 256 + ci0 + ihalf * 16) : Bimg;
            bsz = valid ? 16 : 0;
        } else {
            gA = A + (size_t)(bm * 128 + irow) * Astride + k0 + ihalf * 16;
            gB = Bimg + (size_t)(spbase + irow) * Kch + k0 + ihalf * 16;
        }
        const int r7 = irow & 7;
        #pragma unroll
        for (int c = 0; c < 4; c++) {
            const int ch = ihalf * 4 + c;
            const uint32_t so = irow * 128 + ((ch ^ r7) << 4);
            cpasync(bufA + so, gA + c * 4, 16);
            cpasync(bufB + so, gB + c * 4, bsz);
        }
        cpcommit();
    };

    // ---- warp fragment geometry ----
    const int lane = tid & 31, w = tid >> 5;
    const int wm = (w & 3) << 5, wn = (w >> 2) << 6;
    const int sel = lane >> 3, l7 = lane & 7;
    const int selr = (sel & 1) * 8, selc = sel >> 1;
    int rA[2], rB[4];
    #pragma unroll
    for (int mi = 0; mi < 2; mi++) rA[mi] = wm + mi * 16 + selr + l7;
    #pragma unroll
    for (int np = 0; np < 4; np++) rB[np] = wn + np * 16 + selr + l7;

    float acc[2][8][4];
    #pragma unroll
    for (int i = 0; i < 2; i++)
        #pragma unroll
        for (int j = 0; j < 8; j++)
            #pragma unroll
            for (int q = 0; q < 4; q++) acc[i][j][q] = 0.f;

    issue(0);
    issue(1);

    for (int s = 0; s < NK; s++) {
        if (s + 2 < NK) { issue(s + 2); cpwait<2>(); }
        else if (s + 1 < NK) cpwait<1>();
        else cpwait<0>();
        __syncthreads();

        const uint32_t bufA = sb + (s % 3) * 32768;
        const uint32_t bufB = bufA + 16384;
        #pragma unroll
        for (int kq = 0; kq < 4; kq++) {
            const int c0 = 2 * kq + selc;
            uint32_t a[2][4], b[4][4];
            #pragma unroll
            for (int mi = 0; mi < 2; mi++)
                ldsm4(a[mi], bufA + rA[mi] * 128 + (((c0) ^ (rA[mi] & 7)) << 4));
            #pragma unroll
            for (int np = 0; np < 4; np++)
                ldsm4(b[np], bufB + rB[np] * 128 + (((c0) ^ (rB[np] & 7)) << 4));
            #pragma unroll
            for (int mi = 0; mi < 2; mi++)
                #pragma unroll
                for (int np = 0; np < 4; np++) {
                    mma_tf32(acc[mi][np * 2 + 0], a[mi], b[np][0], b[np][2]);
                    mma_tf32(acc[mi][np * 2 + 1], a[mi], b[np][1], b[np][3]);
                }
        }
        __syncthreads();
    }

    // ---- epilogue ----
    const int g = lane >> 2, tc = lane & 3;

    if (CONV == 3) {
        // direct NCHW store + residual + ReLU
        #pragma unroll
        for (int mi = 0; mi < 2; mi++) {
            const int r0 = bm * 128 + wm + mi * 16 + g;
            const int r1 = r0 + 8;
            const float b0 = bias[r0], b1 = bias[r1];
            const size_t base0 = ((size_t)img * M + r0) * HW + spbase;
            const size_t base1 = ((size_t)img * M + r1) * HW + spbase;
            #pragma unroll
            for (int n8 = 0; n8 < 8; n8++) {
                const int col = wn + n8 * 8 + tc * 2;
                const float2 x0 = *(const float2*)(resid + base0 + col);
                const float2 x1 = *(const float2*)(resid + base1 + col);
                float2 v0, v1;
                v0.x = fmaxf(acc[mi][n8][0] + b0 + x0.x, 0.f);
                v0.y = fmaxf(acc[mi][n8][1] + b0 + x0.y, 0.f);
                v1.x = fmaxf(acc[mi][n8][2] + b1 + x1.x, 0.f);
                v1.y = fmaxf(acc[mi][n8][3] + b1 + x1.y, 0.f);
                *(float2*)(C + base0 + col) = v0;
                *(float2*)(C + base1 + col) = v1;
            }
        }
    } else {
        // transpose via smem staging -> ch-last output, bias+ReLU+tf32 round
        float* st = (float*)smem;                 // [128 sp][68] (64 co + pad)
        #pragma unroll 1
        for (int p = 0; p < 2; p++) {
            __syncthreads();
            if ((wm >> 6) == p) {
                #pragma unroll
                for (int mi = 0; mi < 2; mi++) {
                    const int rg = bm * 128 + wm + mi * 16 + g;
                    const float b0 = bias[rg], b1 = bias[rg + 8];
                    const int c0l = (wm & 63) + mi * 16 + g;
                    #pragma unroll
                    for (int n8 = 0; n8 < 8; n8++) {
                        const int col = wn + n8 * 8 + tc * 2;
                        st[(col)     * 68 + c0l]     = tf(fmaxf(acc[mi][n8][0] + b0, 0.f));
                        st[(col + 1) * 68 + c0l]     = tf(fmaxf(acc[mi][n8][1] + b0, 0.f));
                        st[(col)     * 68 + c0l + 8] = tf(fmaxf(acc[mi][n8][2] + b1, 0.f));
                        st[(col + 1) * 68 + c0l + 8] = tf(fmaxf(acc[mi][n8][3] + b1, 0.f));
                    }
                }
            }
            __syncthreads();
            // readout: coalesced ch-last stores
            const int co8 = (tid & 7) * 8;
            #pragma unroll
            for (int it = 0; it < 4; it++) {
                const int sp = it * 32 + (tid >> 3);
                float* dst = C + ((size_t)img * HW + spbase + sp) * 256
                               + bm * 128 + p * 64 + co8;
                const float* src = st + sp * 68 + co8;
                *(float4*)(dst)     = *(const float4*)(src);
                *(float4*)(dst + 4) = *(const float4*)(src + 4);
            }
        }
    }
}

// ---------------- launch ----------------
extern "C" void kernel_launch(void* const* d_in, const int* in_sizes, int n_in,
                              void* d_out, int out_size)
{
    const float* x  = (const float*)d_in[0];
    const float* w1 = (const float*)d_in[1];
    const float* w2 = (const float*)d_in[2];
    const float* w3 = (const float*)d_in[3];
    const float* s1 = (const float*)d_in[4];
    const float* b1 = (const float*)d_in[5];
    const float* s2 = (const float*)d_in[6];
    const float* b2 = (const float*)d_in[7];
    const float* s3 = (const float*)d_in[8];
    const float* b3 = (const float*)d_in[9];
    float* out = (float*)d_out;

    float *xt, *o1, *o2, *w1s, *w2t, *w3s;
    cudaGetSymbolAddress((void**)&xt,  g_xt);
    cudaGetSymbolAddress((void**)&o1,  g_o1t);
    cudaGetSymbolAddress((void**)&o2,  g_o2t);
    cudaGetSymbolAddress((void**)&w1s, g_w1s);
    cudaGetSymbolAddress((void**)&w2t, g_w2t);
    cudaGetSymbolAddress((void**)&w3s, g_w3s);

    cudaFuncSetAttribute(btl<1>, cudaFuncAttributeMaxDynamicSharedMemorySize, SMEMB);
    cudaFuncSetAttribute(btl<2>, cudaFuncAttributeMaxDynamicSharedMemorySize, SMEMB);
    cudaFuncSetAttribute(btl<3>, cudaFuncAttributeMaxDynamicSharedMemorySize, SMEMB);

    prep_w <<<1024, 256>>>(w1, s1, w1s, 1024);
    prep_w2<<<2304, 256>>>(w2, s2, w2t);
    prep_w <<<1024, 256>>>(w3, s3, w3s, 256);
    transpose_x<<<dim3(32, 32, 32), dim3(32, 8)>>>(x, xt);

    // conv1: M=256, K=1024, B = xt(1024ch)     -> o1 ch-last
    btl<1><<<dim3(8, 2, 32), 256, SMEMB>>>(w1s, xt, o1, b1, nullptr, 256, 1024, 1024, 32);
    // conv2: 3x3, M=256, K=9*256, B = o1(256ch) -> o2 ch-last
    btl<2><<<dim3(8, 2, 32), 256, SMEMB>>>(w2t, o1, o2, b2, nullptr, 256, 256, 256, 72);
    // conv3: M=1024, K=256, B = o2, + resid x   -> out NCHW
    btl<3><<<dim3(8, 8, 32), 256, SMEMB>>>(w3s, o2, out, b3, x, 1024, 256, 256, 8);
}

// round 4
// speedup vs baseline: 2.1571x; 1.9280x over previous
#include <cuda_runtime.h>
#include <cuda_fp16.h>
#include <cstdint>

#define HW 1024
#define N_IMG 32
#define SMEMB 98304   // 3 stages x (16KB A + 16KB B)

// ---------------- device scratch ----------------
__device__ __half g_xh [N_IMG * HW * 1024];   // x ch-last fp16: [img][sp][ci]
__device__ __half g_o1h[N_IMG * HW * 256];    // out1 ch-last fp16
__device__ __half g_o2h[N_IMG * HW * 256];    // out2 ch-last fp16
__device__ __half g_w1h[256 * 1024];
__device__ __half g_w2h[9 * 256 * 256];       // [off][co][ci]
__device__ __half g_w3h[1024 * 256];

__device__ __forceinline__ uint32_t smem_u32(const void* p) {
    uint32_t a;
    asm("{ .reg .u64 t; cvta.to.shared.u64 t, %1; cvt.u32.u64 %0, t; }" : "=r"(a) : "l"(p));
    return a;
}
__device__ __forceinline__ void cpasync(uint32_t s, const void* g, uint32_t srcsz) {
    asm volatile("cp.async.cg.shared.global [%0], [%1], 16, %2;"
                 :: "r"(s), "l"(g), "r"(srcsz) : "memory");
}
__device__ __forceinline__ void cpcommit() { asm volatile("cp.async.commit_group;" ::: "memory"); }
template<int N>
__device__ __forceinline__ void cpwait() { asm volatile("cp.async.wait_group %0;" :: "n"(N) : "memory"); }

__device__ __forceinline__ void ldsm4(uint32_t* r, uint32_t addr) {
    asm volatile("ldmatrix.sync.aligned.m8n8.x4.shared.b16 {%0,%1,%2,%3}, [%4];"
                 : "=r"(r[0]), "=r"(r[1]), "=r"(r[2]), "=r"(r[3]) : "r"(addr));
}
__device__ __forceinline__ void mma_f16(float* d, const uint32_t* a, uint32_t b0, uint32_t b1) {
    asm volatile(
        "mma.sync.aligned.m16n8k16.row.col.f32.f16.f16.f32 "
        "{%0,%1,%2,%3}, {%4,%5,%6,%7}, {%8,%9}, {%0,%1,%2,%3};\n"
        : "+f"(d[0]), "+f"(d[1]), "+f"(d[2]), "+f"(d[3])
        : "r"(a[0]), "r"(a[1]), "r"(a[2]), "r"(a[3]), "r"(b0), "r"(b1));
}

// ---------------- prep kernels ----------------
__global__ void prep_w(const float* __restrict__ w, const float* __restrict__ s,
                       __half* __restrict__ o, int K) {
    int i = blockIdx.x * 256 + threadIdx.x;
    o[i] = __float2half_rn(w[i] * s[i / K]);
}
__global__ void prep_w2(const float* __restrict__ w2, const float* __restrict__ s2,
                        __half* __restrict__ o) {
    int i = blockIdx.x * 256 + threadIdx.x;   // 9*256*256
    int off = i >> 16, rem = i & 65535;
    int co = rem >> 8, ci = rem & 255;
    o[i] = __float2half_rn(w2[co * 2304 + ci * 9 + off] * s2[co]);
}
// x[img][ch][sp] -> xh[img][sp][ch] fp16, 64x64 tiles
__global__ void transpose_x(const float* __restrict__ x, __half* __restrict__ xt) {
    __shared__ float t[64][65];   // t[sp][ch]
    int img = blockIdx.z, ch0 = blockIdx.y * 64, sp0 = blockIdx.x * 64;
    int tx = threadIdx.x, ty = threadIdx.y;    // 32 x 8
    const float* src = x + ((size_t)img * 1024 + ch0) * HW + sp0;
    #pragma unroll
    for (int r = 0; r < 8; r++) {
        int ch = ty + 8 * r;
        t[tx][ch]      = src[ch * HW + tx];
        t[tx + 32][ch] = src[ch * HW + tx + 32];
    }
    __syncthreads();
    __half* dst = xt + ((size_t)img * HW + sp0) * 1024 + ch0;
    #pragma unroll
    for (int r = 0; r < 8; r++) {
        int sp = ty + 8 * r;
        *(__half2*)(dst + sp * 1024 + 2 * tx) =
            __floats2half2_rn(t[sp][2 * tx], t[sp][2 * tx + 1]);
    }
}

// ---------------- main GEMM (fp16 mma, fp32 accum) ----------------
// D[128 co][128 sp] = A[co][k] @ Bt[sp][k]^T, K-contig XOR-swizzled tiles, BK=64.
// CONV: 1 = conv1 (out ch-last fp16), 2 = conv3x3 (out ch-last fp16),
//       3 = conv3 (out NCHW fp32 + residual)
template<int CONV>
__global__ void __launch_bounds__(256, 2)
btl(const __half* __restrict__ A, const __half* __restrict__ Bt,
    void* __restrict__ Cout, const float* __restrict__ bias,
    const float* __restrict__ resid, int M, int Astride, int Kch, int NK)
{
    extern __shared__ char smem[];
    const uint32_t sb = smem_u32(smem);
    const int tid = threadIdx.x;
    const int img = blockIdx.z, bm = blockIdx.y, bn = blockIdx.x;
    const int spbase = bn * 128;
    const __half* Bimg = Bt + (size_t)img * HW * Kch;

    // ---- stage issue: 8 x 16B cp.async per thread ----
    const int irow = tid >> 1;        // 0..127
    const int ihalf = tid & 1;        // 64B half of a 128B row

    auto issue = [&](int s) {
        const uint32_t bufA = sb + (s % 3) * 32768;
        const uint32_t bufB = bufA + 16384;
        const __half* gA;
        const __half* gB;
        uint32_t bsz = 16;
        if (CONV == 2) {
            const int off = s >> 2;               // 4 stages (256 ch) per offset
            const int ci0 = (s & 3) * 64;
            gA = A + off * 65536 + (bm * 128 + irow) * 256 + ci0 + ihalf * 32;
            const int dh = off / 3 - 1, dw = off % 3 - 1;
            const int sp = spbase + irow;
            const int hh = (sp >> 5) + dh, ww = (sp & 31) + dw;
            const bool valid = ((unsigned)hh < 32u) & ((unsigned)ww < 32u);
            gB = valid ? (Bimg + (size_t)((hh << 5) + ww) * 256 + ci0 + ihalf * 32) : Bimg;
            bsz = valid ? 16 : 0;
        } else {
            const int k0 = s * 64;
            gA = A + (size_t)(bm * 128 + irow) * Astride + k0 + ihalf * 32;
            gB = Bimg + (size_t)(spbase + irow) * Kch + k0 + ihalf * 32;
        }
        const int r7 = irow & 7;
        #pragma unroll
        for (int c = 0; c < 4; c++) {
            const int ch = ihalf * 4 + c;
            const uint32_t so = irow * 128 + ((ch ^ r7) << 4);
            cpasync(bufA + so, gA + c * 8, 16);
            cpasync(bufB + so, gB + c * 8, bsz);
        }
        cpcommit();
    };

    // ---- warp fragment geometry ----
    const int lane = tid & 31, w = tid >> 5;
    const int wm = (w & 3) << 5, wn = (w >> 2) << 6;
    const int l7 = lane & 7;
    // A: lanes 0-15 rows +0..15 chunk c, lanes 16-31 same rows chunk c+1
    const int rAl = lane & 15, cA = lane >> 4;
    // B: lanes 0-7 rows+0..7 chunk c, 8-15 rows+0..7 chunk c+1, 16-23 rows+8..15 c, 24-31 c+1
    const int rBl = ((lane >> 4) << 3) + l7, cB = (lane >> 3) & 1;

    float acc[2][8][4];
    #pragma unroll
    for (int i = 0; i < 2; i++)
        #pragma unroll
        for (int j = 0; j < 8; j++)
            #pragma unroll
            for (int q = 0; q < 4; q++) acc[i][j][q] = 0.f;

    issue(0);
    issue(1);

    for (int s = 0; s < NK; s++) {
        if (s + 2 < NK) { issue(s + 2); cpwait<2>(); }
        else if (s + 1 < NK) cpwait<1>();
        else cpwait<0>();
        __syncthreads();

        const uint32_t bufA = sb + (s % 3) * 32768;
        const uint32_t bufB = bufA + 16384;
        #pragma unroll
        for (int kq = 0; kq < 4; kq++) {      // 4 x k16
            uint32_t a[2][4], b[4][4];
            #pragma unroll
            for (int mi = 0; mi < 2; mi++) {
                const int row = wm + mi * 16 + rAl;
                ldsm4(a[mi], bufA + row * 128 + (((2 * kq + cA) ^ l7) << 4));
            }
            #pragma unroll
            for (int np = 0; np < 4; np++) {
                const int row = wn + np * 16 + rBl;
                ldsm4(b[np], bufB + row * 128 + (((2 * kq + cB) ^ l7) << 4));
            }
            #pragma unroll
            for (int mi = 0; mi < 2; mi++)
                #pragma unroll
                for (int np = 0; np < 4; np++) {
                    mma_f16(acc[mi][np * 2 + 0], a[mi], b[np][0], b[np][1]);
                    mma_f16(acc[mi][np * 2 + 1], a[mi], b[np][2], b[np][3]);
                }
        }
        __syncthreads();
    }

    // ---- epilogue ----
    const int g = lane >> 2, tc = lane & 3;

    if (CONV == 3) {
        float* C = (float*)Cout;
        #pragma unroll
        for (int mi = 0; mi < 2; mi++) {
            const int r0 = bm * 128 + wm + mi * 16 + g;
            const int r1 = r0 + 8;
            const float b0 = bias[r0], b1 = bias[r1];
            const size_t base0 = ((size_t)img * M + r0) * HW + spbase;
            const size_t base1 = ((size_t)img * M + r1) * HW + spbase;
            #pragma unroll
            for (int n8 = 0; n8 < 8; n8++) {
                const int col = wn + n8 * 8 + tc * 2;
                const float2 x0 = *(const float2*)(resid + base0 + col);
                const float2 x1 = *(const float2*)(resid + base1 + col);
                float2 v0, v1;
                v0.x = fmaxf(acc[mi][n8][0] + b0 + x0.x, 0.f);
                v0.y = fmaxf(acc[mi][n8][1] + b0 + x0.y, 0.f);
                v1.x = fmaxf(acc[mi][n8][2] + b1 + x1.x, 0.f);
                v1.y = fmaxf(acc[mi][n8][3] + b1 + x1.y, 0.f);
                *(float2*)(C + base0 + col) = v0;
                *(float2*)(C + base1 + col) = v1;
            }
        }
    } else {
        // smem-staged transpose -> ch-last fp16 output, bias+ReLU
        __half* Ch = (__half*)Cout;
        float* st = (float*)smem;                 // [128 sp][68]
        #pragma unroll 1
        for (int p = 0; p < 2; p++) {
            __syncthreads();
            if ((wm >> 6) == p) {
                #pragma unroll
                for (int mi = 0; mi < 2; mi++) {
                    const int rg = bm * 128 + wm + mi * 16 + g;
                    const float b0 = bias[rg], b1 = bias[rg + 8];
                    const int c0l = (wm & 63) + mi * 16 + g;
                    #pragma unroll
                    for (int n8 = 0; n8 < 8; n8++) {
                        const int col = wn + n8 * 8 + tc * 2;
                        st[(col)     * 68 + c0l]     = fmaxf(acc[mi][n8][0] + b0, 0.f);
                        st[(col + 1) * 68 + c0l]     = fmaxf(acc[mi][n8][1] + b0, 0.f);
                        st[(col)     * 68 + c0l + 8] = fmaxf(acc[mi][n8][2] + b1, 0.f);
                        st[(col + 1) * 68 + c0l + 8] = fmaxf(acc[mi][n8][3] + b1, 0.f);
                    }
                }
            }
            __syncthreads();
            const int co8 = (tid & 7) * 8;
            #pragma unroll
            for (int it = 0; it < 4; it++) {
                const int sp = it * 32 + (tid >> 3);
                const float* src = st + sp * 68 + co8;
                __half2 h0 = __floats2half2_rn(src[0], src[1]);
                __half2 h1 = __floats2half2_rn(src[2], src[3]);
                __half2 h2 = __floats2half2_rn(src[4], src[5]);
                __half2 h3 = __floats2half2_rn(src[6], src[7]);
                __half* dst = Ch + ((size_t)img * HW + spbase + sp) * 256
                                 + bm * 128 + p * 64 + co8;
                uint4 pk;
                pk.x = *(uint32_t*)&h0; pk.y = *(uint32_t*)&h1;
                pk.z = *(uint32_t*)&h2; pk.w = *(uint32_t*)&h3;
                *(uint4*)dst = pk;
            }
        }
    }
}

// ---------------- launch ----------------
extern "C" void kernel_launch(void* const* d_in, const int* in_sizes, int n_in,
                              void* d_out, int out_size)
{
    const float* x  = (const float*)d_in[0];
    const float* w1 = (const float*)d_in[1];
    const float* w2 = (const float*)d_in[2];
    const float* w3 = (const float*)d_in[3];
    const float* s1 = (const float*)d_in[4];
    const float* b1 = (const float*)d_in[5];
    const float* s2 = (const float*)d_in[6];
    const float* b2 = (const float*)d_in[7];
    const float* s3 = (const float*)d_in[8];
    const float* b3 = (const float*)d_in[9];
    float* out = (float*)d_out;

    __half *xh, *o1, *o2, *w1h, *w2h, *w3h;
    cudaGetSymbolAddress((void**)&xh,  g_xh);
    cudaGetSymbolAddress((void**)&o1,  g_o1h);
    cudaGetSymbolAddress((void**)&o2,  g_o2h);
    cudaGetSymbolAddress((void**)&w1h, g_w1h);
    cudaGetSymbolAddress((void**)&w2h, g_w2h);
    cudaGetSymbolAddress((void**)&w3h, g_w3h);

    cudaFuncSetAttribute(btl<1>, cudaFuncAttributeMaxDynamicSharedMemorySize, SMEMB);
    cudaFuncSetAttribute(btl<2>, cudaFuncAttributeMaxDynamicSharedMemorySize, SMEMB);
    cudaFuncSetAttribute(btl<3>, cudaFuncAttributeMaxDynamicSharedMemorySize, SMEMB);

    prep_w <<<1024, 256>>>(w1, s1, w1h, 1024);
    prep_w2<<<2304, 256>>>(w2, s2, w2h);
    prep_w <<<1024, 256>>>(w3, s3, w3h, 256);
    transpose_x<<<dim3(16, 16, 32), dim3(32, 8)>>>(x, xh);

    // conv1: M=256, K=1024 (NK=16), B = xh(1024ch)  -> o1 ch-last fp16
    btl<1><<<dim3(8, 2, 32), 256, SMEMB>>>(w1h, xh, o1, b1, nullptr, 256, 1024, 1024, 16);
    // conv2: 3x3, M=256, K=9*256 (NK=36), B = o1    -> o2 ch-last fp16
    btl<2><<<dim3(8, 2, 32), 256, SMEMB>>>(w2h, o1, o2, b2, nullptr, 256, 256, 256, 36);
    // conv3: M=1024, K=256 (NK=4), B = o2, + resid x -> out NCHW fp32
    btl<3><<<dim3(8, 8, 32), 256, SMEMB>>>(w3h, o2, out, b3, x, 1024, 256, 256, 4);
}

// round 5
// speedup vs baseline: 2.1839x; 1.0124x over previous
#include <cuda_runtime.h>
#include <cuda_fp16.h>
#include <cstdint>

#define HW 1024
#define N_IMG 32
#define SMEM_BIG 196608   // 4 stages x (16KB A + 32KB B)
#define SMEM_C3  98304    // 3 stages x (16KB + 16KB)

// ---------------- device scratch ----------------
__device__ __half g_xh [N_IMG * HW * 1024];   // x ch-last fp16
__device__ __half g_o1h[N_IMG * HW * 256];
__device__ __half g_o2h[N_IMG * HW * 256];
__device__ __half g_w1h[256 * 1024];
__device__ __half g_w2h[9 * 256 * 256];       // [off][co][ci]
__device__ __half g_w3h[1024 * 256];

__device__ __forceinline__ uint32_t smem_u32(const void* p) {
    uint32_t a;
    asm("{ .reg .u64 t; cvta.to.shared.u64 t, %1; cvt.u32.u64 %0, t; }" : "=r"(a) : "l"(p));
    return a;
}
__device__ __forceinline__ void cpasync(uint32_t s, const void* g, uint32_t srcsz) {
    asm volatile("cp.async.cg.shared.global [%0], [%1], 16, %2;"
                 :: "r"(s), "l"(g), "r"(srcsz) : "memory");
}
__device__ __forceinline__ void cpcommit() { asm volatile("cp.async.commit_group;" ::: "memory"); }
template<int N>
__device__ __forceinline__ void cpwait() { asm volatile("cp.async.wait_group %0;" :: "n"(N) : "memory"); }

__device__ __forceinline__ void ldsm4(uint32_t* r, uint32_t addr) {
    asm volatile("ldmatrix.sync.aligned.m8n8.x4.shared.b16 {%0,%1,%2,%3}, [%4];"
                 : "=r"(r[0]), "=r"(r[1]), "=r"(r[2]), "=r"(r[3]) : "r"(addr));
}
__device__ __forceinline__ void mma_f16(float* d, const uint32_t* a, uint32_t b0, uint32_t b1) {
    asm volatile(
        "mma.sync.aligned.m16n8k16.row.col.f32.f16.f16.f32 "
        "{%0,%1,%2,%3}, {%4,%5,%6,%7}, {%8,%9}, {%0,%1,%2,%3};\n"
        : "+f"(d[0]), "+f"(d[1]), "+f"(d[2]), "+f"(d[3])
        : "r"(a[0]), "r"(a[1]), "r"(a[2]), "r"(a[3]), "r"(b0), "r"(b1));
}

// ---------------- prep kernels ----------------
__global__ void prep_w(const float* __restrict__ w, const float* __restrict__ s,
                       __half* __restrict__ o, int K) {
    int i = blockIdx.x * 256 + threadIdx.x;
    o[i] = __float2half_rn(w[i] * s[i / K]);
}
__global__ void prep_w2(const float* __restrict__ w2, const float* __restrict__ s2,
                        __half* __restrict__ o) {
    int i = blockIdx.x * 256 + threadIdx.x;   // 9*256*256
    int off = i >> 16, rem = i & 65535;
    int co = rem >> 8, ci = rem & 255;
    o[i] = __float2half_rn(w2[co * 2304 + ci * 9 + off] * s2[co]);
}
__global__ void transpose_x(const float* __restrict__ x, __half* __restrict__ xt) {
    __shared__ float t[64][65];
    int img = blockIdx.z, ch0 = blockIdx.y * 64, sp0 = blockIdx.x * 64;
    int tx = threadIdx.x, ty = threadIdx.y;    // 32 x 8
    const float* src = x + ((size_t)img * 1024 + ch0) * HW + sp0;
    #pragma unroll
    for (int r = 0; r < 8; r++) {
        int ch = ty + 8 * r;
        t[tx][ch]      = src[ch * HW + tx];
        t[tx + 32][ch] = src[ch * HW + tx + 32];
    }
    __syncthreads();
    __half* dst = xt + ((size_t)img * HW + sp0) * 1024 + ch0;
    #pragma unroll
    for (int r = 0; r < 8; r++) {
        int sp = ty + 8 * r;
        *(__half2*)(dst + sp * 1024 + 2 * tx) =
            __floats2half2_rn(t[sp][2 * tx], t[sp][2 * tx + 1]);
    }
}

// ---------------- big-tile GEMM for conv1/conv2 ----------------
// CTA tile 128(co) x 256(sp), warp tile 64x64, BK=64, 4-stage cp.async, 1 sync/stage.
template<int CONV>   // 1 = conv1x1, 2 = conv3x3 implicit
__global__ void __launch_bounds__(256, 1)
btl_big(const __half* __restrict__ A, const __half* __restrict__ Bt,
        __half* __restrict__ Cout, const float* __restrict__ bias,
        int Astride, int Kch, int NK)
{
    extern __shared__ char smem[];
    const uint32_t sb = smem_u32(smem);
    const int tid = threadIdx.x;
    const int img = blockIdx.z, bm = blockIdx.y, bn = blockIdx.x;
    const int spbase = bn * 256;
    const __half* Bimg = Bt + (size_t)img * HW * Kch;

    const int irow = tid >> 1, ihalf = tid & 1;

    auto issue = [&](int s) {
        const uint32_t bufA = sb + (s & 3) * 49152;
        const uint32_t bufB = bufA + 16384;
        const __half *gA, *gB0, *gB1;
        uint32_t bsz0 = 16, bsz1 = 16;
        if (CONV == 2) {
            const int off = s >> 2, ci0 = (s & 3) * 64;
            gA = A + off * 65536 + (bm * 128 + irow) * 256 + ci0 + ihalf * 32;
            const int dh = off / 3 - 1, dw = off % 3 - 1;
            {
                const int sp = spbase + irow;
                const int hh = (sp >> 5) + dh, ww = (sp & 31) + dw;
                const bool v = ((unsigned)hh < 32u) & ((unsigned)ww < 32u);
                gB0 = v ? Bimg + (size_t)((hh << 5) + ww) * 256 + ci0 + ihalf * 32 : Bimg;
                bsz0 = v ? 16 : 0;
            }
            {
                const int sp = spbase + irow + 128;
                const int hh = (sp >> 5) + dh, ww = (sp & 31) + dw;
                const bool v = ((unsigned)hh < 32u) & ((unsigned)ww < 32u);
                gB1 = v ? Bimg + (size_t)((hh << 5) + ww) * 256 + ci0 + ihalf * 32 : Bimg;
                bsz1 = v ? 16 : 0;
            }
        } else {
            const int k0 = s * 64;
            gA  = A + (size_t)(bm * 128 + irow) * Astride + k0 + ihalf * 32;
            gB0 = Bimg + (size_t)(spbase + irow) * Kch + k0 + ihalf * 32;
            gB1 = gB0 + (size_t)128 * Kch;
        }
        const int r7 = irow & 7;
        #pragma unroll
        for (int c = 0; c < 4; c++) {
            const int ch = ihalf * 4 + c;
            const uint32_t so = irow * 128 + ((ch ^ r7) << 4);
            cpasync(bufA + so,         gA  + c * 8, 16);
            cpasync(bufB + so,         gB0 + c * 8, bsz0);
            cpasync(bufB + 16384 + so, gB1 + c * 8, bsz1);
        }
        cpcommit();
    };

    const int lane = tid & 31, w = tid >> 5;
    const int wm = (w & 1) * 64, wn = (w >> 1) * 64;
    const int l7 = lane & 7;
    const int rAl = lane & 15, cA = lane >> 4;
    const int rBl = ((lane >> 4) << 3) + l7, cB = (lane >> 3) & 1;

    float acc[4][8][4];
    #pragma unroll
    for (int i = 0; i < 4; i++)
        #pragma unroll
        for (int j = 0; j < 8; j++)
            #pragma unroll
            for (int q = 0; q < 4; q++) acc[i][j][q] = 0.f;

    issue(0); issue(1); issue(2);

    for (int s = 0; s < NK; s++) {
        if (s + 2 < NK) cpwait<2>();
        else if (s + 1 < NK) cpwait<1>();
        else cpwait<0>();
        __syncthreads();
        if (s + 3 < NK) issue(s + 3);

        const uint32_t bufA = sb + (s & 3) * 49152;
        const uint32_t bufB = bufA + 16384;
        #pragma unroll
        for (int kq = 0; kq < 4; kq++) {
            uint32_t a[4][4], b[4][4];
            #pragma unroll
            for (int mi = 0; mi < 4; mi++) {
                const int row = wm + mi * 16 + rAl;
                ldsm4(a[mi], bufA + row * 128 + (((2 * kq + cA) ^ l7) << 4));
            }
            #pragma unroll
            for (int np = 0; np < 4; np++) {
                const int row = wn + np * 16 + rBl;
                ldsm4(b[np], bufB + row * 128 + (((2 * kq + cB) ^ l7) << 4));
            }
            #pragma unroll
            for (int mi = 0; mi < 4; mi++)
                #pragma unroll
                for (int np = 0; np < 4; np++) {
                    mma_f16(acc[mi][np * 2 + 0], a[mi], b[np][0], b[np][1]);
                    mma_f16(acc[mi][np * 2 + 1], a[mi], b[np][2], b[np][3]);
                }
        }
    }

    // ---- epilogue: per-warp 64x64 smem staging -> ch-last fp16, bias+ReLU ----
    __syncthreads();
    float* stw = (float*)smem + w * (64 * 68);
    const int g = lane >> 2, tc = lane & 3;
    #pragma unroll
    for (int mi = 0; mi < 4; mi++) {
        const int rg = bm * 128 + wm + mi * 16 + g;
        const float b0 = bias[rg], b1 = bias[rg + 8];
        const int col = mi * 16 + g;
        #pragma unroll
        for (int n8 = 0; n8 < 8; n8++) {
            const int spl = n8 * 8 + tc * 2;
            stw[spl * 68 + col]           = fmaxf(acc[mi][n8][0] + b0, 0.f);
            stw[(spl + 1) * 68 + col]     = fmaxf(acc[mi][n8][1] + b0, 0.f);
            stw[spl * 68 + col + 8]       = fmaxf(acc[mi][n8][2] + b1, 0.f);
            stw[(spl + 1) * 68 + col + 8] = fmaxf(acc[mi][n8][3] + b1, 0.f);
        }
    }
    __syncwarp();
    const int co8 = (lane & 7) * 8, spr = lane >> 3;
    #pragma unroll
    for (int it = 0; it < 16; it++) {
        const int spl = spr + it * 4;
        const float* src = stw + spl * 68 + co8;
        __half2 h0 = __floats2half2_rn(src[0], src[1]);
        __half2 h1 = __floats2half2_rn(src[2], src[3]);
        __half2 h2 = __floats2half2_rn(src[4], src[5]);
        __half2 h3 = __floats2half2_rn(src[6], src[7]);
        __half* dst = Cout + ((size_t)img * HW + spbase + wn + spl) * 256
                           + bm * 128 + wm + co8;
        uint4 pk;
        pk.x = *(uint32_t*)&h0; pk.y = *(uint32_t*)&h1;
        pk.z = *(uint32_t*)&h2; pk.w = *(uint32_t*)&h3;
        *(uint4*)dst = pk;
    }
}

// ---------------- conv3: R4 geometry (2 CTA/SM, mem-bound friendly) ----------------
__global__ void __launch_bounds__(256, 2)
btl3(const __half* __restrict__ A, const __half* __restrict__ Bt,
     float* __restrict__ C, const float* __restrict__ bias,
     const float* __restrict__ resid, int NK)
{
    extern __shared__ char smem[];
    const uint32_t sb = smem_u32(smem);
    const int tid = threadIdx.x;
    const int img = blockIdx.z, bm = blockIdx.y, bn = blockIdx.x;
    const int spbase = bn * 128;
    const __half* Bimg = Bt + (size_t)img * HW * 256;

    const int irow = tid >> 1, ihalf = tid & 1;
    auto issue = [&](int s) {
        const uint32_t bufA = sb + (s % 3) * 32768;
        const uint32_t bufB = bufA + 16384;
        const int k0 = s * 64;
        const __half* gA = A + (size_t)(bm * 128 + irow) * 256 + k0 + ihalf * 32;
        const __half* gB = Bimg + (size_t)(spbase + irow) * 256 + k0 + ihalf * 32;
        const int r7 = irow & 7;
        #pragma unroll
        for (int c = 0; c < 4; c++) {
            const int ch = ihalf * 4 + c;
            const uint32_t so = irow * 128 + ((ch ^ r7) << 4);
            cpasync(bufA + so, gA + c * 8, 16);
            cpasync(bufB + so, gB + c * 8, 16);
        }
        cpcommit();
    };

    const int lane = tid & 31, w = tid >> 5;
    const int wm = (w & 3) << 5, wn = (w >> 2) << 6;
    const int l7 = lane & 7;
    const int rAl = lane & 15, cA = lane >> 4;
    const int rBl = ((lane >> 4) << 3) + l7, cB = (lane >> 3) & 1;

    float acc[2][8][4];
    #pragma unroll
    for (int i = 0; i < 2; i++)
        #pragma unroll
        for (int j = 0; j < 8; j++)
            #pragma unroll
            for (int q = 0; q < 4; q++) acc[i][j][q] = 0.f;

    issue(0); issue(1);

    for (int s = 0; s < NK; s++) {
        if (s + 2 < NK) { issue(s + 2); cpwait<2>(); }
        else if (s + 1 < NK) cpwait<1>();
        else cpwait<0>();
        __syncthreads();

        const uint32_t bufA = sb + (s % 3) * 32768;
        const uint32_t bufB = bufA + 16384;
        #pragma unroll
        for (int kq = 0; kq < 4; kq++) {
            uint32_t a[2][4], b[4][4];
            #pragma unroll
            for (int mi = 0; mi < 2; mi++) {
                const int row = wm + mi * 16 + rAl;
                ldsm4(a[mi], bufA + row * 128 + (((2 * kq + cA) ^ l7) << 4));
            }
            #pragma unroll
            for (int np = 0; np < 4; np++) {
                const int row = wn + np * 16 + rBl;
                ldsm4(b[np], bufB + row * 128 + (((2 * kq + cB) ^ l7) << 4));
            }
            #pragma unroll
            for (int mi = 0; mi < 2; mi++)
                #pragma unroll
                for (int np = 0; np < 4; np++) {
                    mma_f16(acc[mi][np * 2 + 0], a[mi], b[np][0], b[np][1]);
                    mma_f16(acc[mi][np * 2 + 1], a[mi], b[np][2], b[np][3]);
                }
        }
        __syncthreads();
    }

    const int g = lane >> 2, tc = lane & 3;
    #pragma unroll
    for (int mi = 0; mi < 2; mi++) {
        const int r0 = bm * 128 + wm + mi * 16 + g;
        const int r1 = r0 + 8;
        const float b0 = bias[r0], b1 = bias[r1];
        const size_t base0 = ((size_t)img * 1024 + r0) * HW + spbase;
        const size_t base1 = ((size_t)img * 1024 + r1) * HW + spbase;
        #pragma unroll
        for (int n8 = 0; n8 < 8; n8++) {
            const int col = wn + n8 * 8 + tc * 2;
            const float2 x0 = *(const float2*)(resid + base0 + col);
            const float2 x1 = *(const float2*)(resid + base1 + col);
            float2 v0, v1;
            v0.x = fmaxf(acc[mi][n8][0] + b0 + x0.x, 0.f);
            v0.y = fmaxf(acc[mi][n8][1] + b0 + x0.y, 0.f);
            v1.x = fmaxf(acc[mi][n8][2] + b1 + x1.x, 0.f);
            v1.y = fmaxf(acc[mi][n8][3] + b1 + x1.y, 0.f);
            *(float2*)(C + base0 + col) = v0;
            *(float2*)(C + base1 + col) = v1;
        }
    }
}

// ---------------- launch ----------------
extern "C" void kernel_launch(void* const* d_in, const int* in_sizes, int n_in,
                              void* d_out, int out_size)
{
    const float* x  = (const float*)d_in[0];
    const float* w1 = (const float*)d_in[1];
    const float* w2 = (const float*)d_in[2];
    const float* w3 = (const float*)d_in[3];
    const float* s1 = (const float*)d_in[4];
    const float* b1 = (const float*)d_in[5];
    const float* s2 = (const float*)d_in[6];
    const float* b2 = (const float*)d_in[7];
    const float* s3 = (const float*)d_in[8];
    const float* b3 = (const float*)d_in[9];
    float* out = (float*)d_out;

    __half *xh, *o1, *o2, *w1h, *w2h, *w3h;
    cudaGetSymbolAddress((void**)&xh,  g_xh);
    cudaGetSymbolAddress((void**)&o1,  g_o1h);
    cudaGetSymbolAddress((void**)&o2,  g_o2h);
    cudaGetSymbolAddress((void**)&w1h, g_w1h);
    cudaGetSymbolAddress((void**)&w2h, g_w2h);
    cudaGetSymbolAddress((void**)&w3h, g_w3h);

    cudaFuncSetAttribute(btl_big<1>, cudaFuncAttributeMaxDynamicSharedMemorySize, SMEM_BIG);
    cudaFuncSetAttribute(btl_big<2>, cudaFuncAttributeMaxDynamicSharedMemorySize, SMEM_BIG);
    cudaFuncSetAttribute(btl3,       cudaFuncAttributeMaxDynamicSharedMemorySize, SMEM_C3);

    prep_w <<<1024, 256>>>(w1, s1, w1h, 1024);
    prep_w2<<<2304, 256>>>(w2, s2, w2h);
    prep_w <<<1024, 256>>>(w3, s3, w3h, 256);
    transpose_x<<<dim3(16, 16, 32), dim3(32, 8)>>>(x, xh);

    // conv1: M=256, K=1024 (NK=16)
    btl_big<1><<<dim3(4, 2, 32), 256, SMEM_BIG>>>(w1h, xh, o1, b1, 1024, 1024, 16);
    // conv2: 3x3, K=9*256 (NK=36)
    btl_big<2><<<dim3(4, 2, 32), 256, SMEM_BIG>>>(w2h, o1, o2, b2, 0, 256, 36);
    // conv3: M=1024, K=256 (NK=4), + residual
    btl3<<<dim3(8, 8, 32), 256, SMEM_C3>>>(w3h, o2, out, b3, x, 4);
}

// round 6
// speedup vs baseline: 2.2797x; 1.0439x over previous
#include <cuda_runtime.h>
#include <cuda_fp16.h>
#include <cstdint>

#define HW 1024
#define N_IMG 32
#define SMEM_C1 139264    // max(4x16KB A + 2x32KB B, epilogue 8x64x68x4)
#define SMEM_BIG 196608   // conv2: 4 stages x (16KB A + 32KB B)
#define SMEM_C3  98304    // conv3: 3 stages x (16KB + 16KB)

// ---------------- device scratch ----------------
__device__ __half g_o1h[N_IMG * HW * 256];
__device__ __half g_o2h[N_IMG * HW * 256];
__device__ __half g_w1h[256 * 1024];
__device__ __half g_w2h[9 * 256 * 256];       // [off][co][ci]
__device__ __half g_w3h[1024 * 256];

__device__ __forceinline__ uint32_t smem_u32(const void* p) {
    uint32_t a;
    asm("{ .reg .u64 t; cvta.to.shared.u64 t, %1; cvt.u32.u64 %0, t; }" : "=r"(a) : "l"(p));
    return a;
}
__device__ __forceinline__ void cpasync(uint32_t s, const void* g, uint32_t srcsz) {
    asm volatile("cp.async.cg.shared.global [%0], [%1], 16, %2;"
                 :: "r"(s), "l"(g), "r"(srcsz) : "memory");
}
__device__ __forceinline__ void cpcommit() { asm volatile("cp.async.commit_group;" ::: "memory"); }
template<int N>
__device__ __forceinline__ void cpwait() { asm volatile("cp.async.wait_group %0;" :: "n"(N) : "memory"); }

__device__ __forceinline__ void ldsm4(uint32_t* r, uint32_t addr) {
    asm volatile("ldmatrix.sync.aligned.m8n8.x4.shared.b16 {%0,%1,%2,%3}, [%4];"
                 : "=r"(r[0]), "=r"(r[1]), "=r"(r[2]), "=r"(r[3]) : "r"(addr));
}
__device__ __forceinline__ void mma_f16(float* d, const uint32_t* a, uint32_t b0, uint32_t b1) {
    asm volatile(
        "mma.sync.aligned.m16n8k16.row.col.f32.f16.f16.f32 "
        "{%0,%1,%2,%3}, {%4,%5,%6,%7}, {%8,%9}, {%0,%1,%2,%3};\n"
        : "+f"(d[0]), "+f"(d[1]), "+f"(d[2]), "+f"(d[3])
        : "r"(a[0]), "r"(a[1]), "r"(a[2]), "r"(a[3]), "r"(b0), "r"(b1));
}

// ---------------- prep kernels ----------------
__global__ void prep_w(const float* __restrict__ w, const float* __restrict__ s,
                       __half* __restrict__ o, int K) {
    int i = blockIdx.x * 256 + threadIdx.x;
    o[i] = __float2half_rn(w[i] * s[i / K]);
}
__global__ void prep_w2(const float* __restrict__ w2, const float* __restrict__ s2,
                        __half* __restrict__ o) {
    int i = blockIdx.x * 256 + threadIdx.x;   // 9*256*256
    int off = i >> 16, rem = i & 65535;
    int co = rem >> 8, ci = rem & 255;
    o[i] = __float2half_rn(w2[co * 2304 + ci * 9 + off] * s2[co]);
}

// ---------------- shared epilogue: per-warp 64x64 staging -> ch-last fp16 ----------------
__device__ __forceinline__ void epilogue_chlast(
    char* smem, float acc[4][8][4], __half* Cout, const float* bias,
    int img, int bm, int spbase, int wm, int wn, int w, int lane)
{
    float* stw = (float*)smem + w * (64 * 68);
    const int g = lane >> 2, tc = lane & 3;
    #pragma unroll
    for (int mi = 0; mi < 4; mi++) {
        const int rg = bm * 128 + wm + mi * 16 + g;
        const float b0 = bias[rg], b1 = bias[rg + 8];
        const int col = mi * 16 + g;
        #pragma unroll
        for (int n8 = 0; n8 < 8; n8++) {
            const int spl = n8 * 8 + tc * 2;
            stw[spl * 68 + col]           = fmaxf(acc[mi][n8][0] + b0, 0.f);
            stw[(spl + 1) * 68 + col]     = fmaxf(acc[mi][n8][1] + b0, 0.f);
            stw[spl * 68 + col + 8]       = fmaxf(acc[mi][n8][2] + b1, 0.f);
            stw[(spl + 1) * 68 + col + 8] = fmaxf(acc[mi][n8][3] + b1, 0.f);
        }
    }
    __syncwarp();
    const int co8 = (lane & 7) * 8, spr = lane >> 3;
    #pragma unroll
    for (int it = 0; it < 16; it++) {
        const int spl = spr + it * 4;
        const float* src = stw + spl * 68 + co8;
        __half2 h0 = __floats2half2_rn(src[0], src[1]);
        __half2 h1 = __floats2half2_rn(src[2], src[3]);
        __half2 h2 = __floats2half2_rn(src[4], src[5]);
        __half2 h3 = __floats2half2_rn(src[6], src[7]);
        __half* dst = Cout + ((size_t)img * HW + spbase + wn + spl) * 256
                           + bm * 128 + wm + co8;
        uint4 pk;
        pk.x = *(uint32_t*)&h0; pk.y = *(uint32_t*)&h1;
        pk.z = *(uint32_t*)&h2; pk.w = *(uint32_t*)&h3;
        *(uint4*)dst = pk;
    }
}

// ---------------- conv1: fused NCHW->ch-last transpose + GEMM ----------------
// CTA 128co x 256sp, BK=64, 16 stages. A: cp.async 4-deep. B: LDG(fp32, transposed
// gather) -> regs -> cvt -> STS.128 swizzled, double-buffered.
__global__ void __launch_bounds__(256, 1)
btl1f(const __half* __restrict__ A, const float* __restrict__ X,
      __half* __restrict__ Cout, const float* __restrict__ bias)
{
    extern __shared__ char smem[];
    const uint32_t sb = smem_u32(smem);
    const int tid = threadIdx.x;
    const int img = blockIdx.z, bm = blockIdx.y, bn = blockIdx.x;
    const int spbase = bn * 256;
    const float* Ximg = X + (size_t)img * 1024 * HW;

    const int irow = tid >> 1, ihalf = tid & 1;
    auto issueA = [&](int s) {
        const uint32_t bufA = sb + (s & 3) * 16384;
        const __half* gA = A + (size_t)(bm * 128 + irow) * 1024 + s * 64 + ihalf * 32;
        const int r7 = irow & 7;
        #pragma unroll
        for (int c = 0; c < 4; c++) {
            const int ch = ihalf * 4 + c;
            cpasync(bufA + irow * 128 + ((ch ^ r7) << 4), gA + c * 8, 16);
        }
        cpcommit();
    };

    // B: 8 units/thread; unit u -> sp = u&255, ci-group cig = u>>8 (8 ci each)
    uint32_t breg[8][4];
    auto ldB = [&](int s) {
        #pragma unroll
        for (int it = 0; it < 8; it++) {
            const int u = tid + it * 256;
            const int sp = u & 255, cig = u >> 8;
            const float* g = Ximg + (size_t)(s * 64 + cig * 8) * HW + spbase + sp;
            float v0 = g[0],      v1 = g[HW],     v2 = g[2 * HW], v3 = g[3 * HW];
            float v4 = g[4 * HW], v5 = g[5 * HW], v6 = g[6 * HW], v7 = g[7 * HW];
            __half2 h0 = __floats2half2_rn(v0, v1);
            __half2 h1 = __floats2half2_rn(v2, v3);
            __half2 h2 = __floats2half2_rn(v4, v5);
            __half2 h3 = __floats2half2_rn(v6, v7);
            breg[it][0] = *(uint32_t*)&h0; breg[it][1] = *(uint32_t*)&h1;
            breg[it][2] = *(uint32_t*)&h2; breg[it][3] = *(uint32_t*)&h3;
        }
    };
    auto stsB = [&](int s) {
        char* bufB = smem + 65536 + (s & 1) * 32768;
        #pragma unroll
        for (int it = 0; it < 8; it++) {
            const int u = tid + it * 256;
            const int sp = u & 255, cig = u >> 8;
            uint4 pk;
            pk.x = breg[it][0]; pk.y = breg[it][1];
            pk.z = breg[it][2]; pk.w = breg[it][3];
            *(uint4*)(bufB + sp * 128 + ((cig ^ (sp & 7)) << 4)) = pk;
        }
    };

    const int lane = tid & 31, w = tid >> 5;
    const int wm = (w & 1) * 64, wn = (w >> 1) * 64;
    const int l7 = lane & 7;
    const int rAl = lane & 15, cA = lane >> 4;
    const int rBl = ((lane >> 4) << 3) + l7, cB = (lane >> 3) & 1;

    float acc[4][8][4];
    #pragma unroll
    for (int i = 0; i < 4; i++)
        #pragma unroll
        for (int j = 0; j < 8; j++)
            #pragma unroll
            for (int q = 0; q < 4; q++) acc[i][j][q] = 0.f;

    ldB(0); stsB(0);
    issueA(0); issueA(1); issueA(2);

    const int NS = 16;
    for (int s = 0; s < NS; s++) {
        cpwait<2>();
        __syncthreads();     // A(s) + B(s) visible; prior-stage consumers done
        if (s + 1 < NS) ldB(s + 1);

        const uint32_t bufA = sb + (s & 3) * 16384;
        const uint32_t bufB = sb + 65536 + (s & 1) * 32768;
        #pragma unroll
        for (int kq = 0; kq < 4; kq++) {
            uint32_t a[4][4], b[4][4];
            #pragma unroll
            for (int mi = 0; mi < 4; mi++) {
                const int row = wm + mi * 16 + rAl;
                ldsm4(a[mi], bufA + row * 128 + (((2 * kq + cA) ^ l7) << 4));
            }
            #pragma unroll
            for (int np = 0; np < 4; np++) {
                const int row = wn + np * 16 + rBl;
                ldsm4(b[np], bufB + row * 128 + (((2 * kq + cB) ^ l7) << 4));
            }
            #pragma unroll
            for (int mi = 0; mi < 4; mi++)
                #pragma unroll
                for (int np = 0; np < 4; np++) {
                    mma_f16(acc[mi][np * 2 + 0], a[mi], b[np][0], b[np][1]);
                    mma_f16(acc[mi][np * 2 + 1], a[mi], b[np][2], b[np][3]);
                }
        }
        if (s + 3 < NS) issueA(s + 3); else cpcommit();
        if (s + 1 < NS) stsB(s + 1);
    }

    __syncthreads();
    epilogue_chlast(smem, acc, Cout, bias, img, bm, spbase, wm, wn, w, lane);
}

// ---------------- conv2: big-tile implicit 3x3 (unchanged from R5) ----------------
__global__ void __launch_bounds__(256, 1)
btl2(const __half* __restrict__ A, const __half* __restrict__ Bt,
     __half* __restrict__ Cout, const float* __restrict__ bias)
{
    extern __shared__ char smem[];
    const uint32_t sb = smem_u32(smem);
    const int tid = threadIdx.x;
    const int img = blockIdx.z, bm = blockIdx.y, bn = blockIdx.x;
    const int spbase = bn * 256;
    const __half* Bimg = Bt + (size_t)img * HW * 256;

    const int irow = tid >> 1, ihalf = tid & 1;
    auto issue = [&](int s) {
        const uint32_t bufA = sb + (s & 3) * 49152;
        const uint32_t bufB = bufA + 16384;
        const int off = s >> 2, ci0 = (s & 3) * 64;
        const __half* gA = A + off * 65536 + (bm * 128 + irow) * 256 + ci0 + ihalf * 32;
        const int dh = off / 3 - 1, dw = off % 3 - 1;
        const __half *gB0, *gB1;
        uint32_t bsz0, bsz1;
        {
            const int sp = spbase + irow;
            const int hh = (sp >> 5) + dh, ww = (sp & 31) + dw;
            const bool v = ((unsigned)hh < 32u) & ((unsigned)ww < 32u);
            gB0 = v ? Bimg + (size_t)((hh << 5) + ww) * 256 + ci0 + ihalf * 32 : Bimg;
            bsz0 = v ? 16 : 0;
        }
        {
            const int sp = spbase + irow + 128;
            const int hh = (sp >> 5) + dh, ww = (sp & 31) + dw;
            const bool v = ((unsigned)hh < 32u) & ((unsigned)ww < 32u);
            gB1 = v ? Bimg + (size_t)((hh << 5) + ww) * 256 + ci0 + ihalf * 32 : Bimg;
            bsz1 = v ? 16 : 0;
        }
        const int r7 = irow & 7;
        #pragma unroll
        for (int c = 0; c < 4; c++) {
            const int ch = ihalf * 4 + c;
            const uint32_t so = irow * 128 + ((ch ^ r7) << 4);
            cpasync(bufA + so,         gA  + c * 8, 16);
            cpasync(bufB + so,         gB0 + c * 8, bsz0);
            cpasync(bufB + 16384 + so, gB1 + c * 8, bsz1);
        }
        cpcommit();
    };

    const int lane = tid & 31, w = tid >> 5;
    const int wm = (w & 1) * 64, wn = (w >> 1) * 64;
    const int l7 = lane & 7;
    const int rAl = lane & 15, cA = lane >> 4;
    const int rBl = ((lane >> 4) << 3) + l7, cB = (lane >> 3) & 1;

    float acc[4][8][4];
    #pragma unroll
    for (int i = 0; i < 4; i++)
        #pragma unroll
        for (int j = 0; j < 8; j++)
            #pragma unroll
            for (int q = 0; q < 4; q++) acc[i][j][q] = 0.f;

    issue(0); issue(1); issue(2);

    const int NS = 36;
    for (int s = 0; s < NS; s++) {
        if (s + 2 < NS) cpwait<2>();
        else if (s + 1 < NS) cpwait<1>();
        else cpwait<0>();
        __syncthreads();
        if (s + 3 < NS) issue(s + 3);

        const uint32_t bufA = sb + (s & 3) * 49152;
        const uint32_t bufB = bufA + 16384;
        #pragma unroll
        for (int kq = 0; kq < 4; kq++) {
            uint32_t a[4][4], b[4][4];
            #pragma unroll
            for (int mi = 0; mi < 4; mi++) {
                const int row = wm + mi * 16 + rAl;
                ldsm4(a[mi], bufA + row * 128 + (((2 * kq + cA) ^ l7) << 4));
            }
            #pragma unroll
            for (int np = 0; np < 4; np++) {
                const int row = wn + np * 16 + rBl;
                ldsm4(b[np], bufB + row * 128 + (((2 * kq + cB) ^ l7) << 4));
            }
            #pragma unroll
            for (int mi = 0; mi < 4; mi++)
                #pragma unroll
                for (int np = 0; np < 4; np++) {
                    mma_f16(acc[mi][np * 2 + 0], a[mi], b[np][0], b[np][1]);
                    mma_f16(acc[mi][np * 2 + 1], a[mi], b[np][2], b[np][3]);
                }
        }
    }

    __syncthreads();
    epilogue_chlast(smem, acc, Cout, bias, img, bm, spbase, wm, wn, w, lane);
}

// ---------------- conv3: 2 CTA/SM, residual + NCHW fp32 out (unchanged) ----------------
__global__ void __launch_bounds__(256, 2)
btl3(const __half* __restrict__ A, const __half* __restrict__ Bt,
     float* __restrict__ C, const float* __restrict__ bias,
     const float* __restrict__ resid)
{
    extern __shared__ char smem[];
    const uint32_t sb = smem_u32(smem);
    const int tid = threadIdx.x;
    const int img = blockIdx.z, bm = blockIdx.y, bn = blockIdx.x;
    const int spbase = bn * 128;
    const __half* Bimg = Bt + (size_t)img * HW * 256;

    const int irow = tid >> 1, ihalf = tid & 1;
    auto issue = [&](int s) {
        const uint32_t bufA = sb + (s % 3) * 32768;
        const uint32_t bufB = bufA + 16384;
        const int k0 = s * 64;
        const __half* gA = A + (size_t)(bm * 128 + irow) * 256 + k0 + ihalf * 32;
        const __half* gB = Bimg + (size_t)(spbase + irow) * 256 + k0 + ihalf * 32;
        const int r7 = irow & 7;
        #pragma unroll
        for (int c = 0; c < 4; c++) {
            const int ch = ihalf * 4 + c;
            const uint32_t so = irow * 128 + ((ch ^ r7) << 4);
            cpasync(bufA + so, gA + c * 8, 16);
            cpasync(bufB + so, gB + c * 8, 16);
        }
        cpcommit();
    };

    const int lane = tid & 31, w = tid >> 5;
    const int wm = (w & 3) << 5, wn = (w >> 2) << 6;
    const int l7 = lane & 7;
    const int rAl = lane & 15, cA = lane >> 4;
    const int rBl = ((lane >> 4) << 3) + l7, cB = (lane >> 3) & 1;

    float acc[2][8][4];
    #pragma unroll
    for (int i = 0; i < 2; i++)
        #pragma unroll
        for (int j = 0; j < 8; j++)
            #pragma unroll
            for (int q = 0; q < 4; q++) acc[i][j][q] = 0.f;

    issue(0); issue(1);
    const int NS = 4;
    for (int s = 0; s < NS; s++) {
        if (s + 2 < NS) { issue(s + 2); cpwait<2>(); }
        else if (s + 1 < NS) cpwait<1>();
        else cpwait<0>();
        __syncthreads();

        const uint32_t bufA = sb + (s % 3) * 32768;
        const uint32_t bufB = bufA + 16384;
        #pragma unroll
        for (int kq = 0; kq < 4; kq++) {
            uint32_t a[2][4], b[4][4];
            #pragma unroll
            for (int mi = 0; mi < 2; mi++) {
                const int row = wm + mi * 16 + rAl;
                ldsm4(a[mi], bufA + row * 128 + (((2 * kq + cA) ^ l7) << 4));
            }
            #pragma unroll
            for (int np = 0; np < 4; np++) {
                const int row = wn + np * 16 + rBl;
                ldsm4(b[np], bufB + row * 128 + (((2 * kq + cB) ^ l7) << 4));
            }
            #pragma unroll
            for (int mi = 0; mi < 2; mi++)
                #pragma unroll
                for (int np = 0; np < 4; np++) {
                    mma_f16(acc[mi][np * 2 + 0], a[mi], b[np][0], b[np][1]);
                    mma_f16(acc[mi][np * 2 + 1], a[mi], b[np][2], b[np][3]);
                }
        }
        __syncthreads();
    }

    const int g = lane >> 2, tc = lane & 3;
    #pragma unroll
    for (int mi = 0; mi < 2; mi++) {
        const int r0 = bm * 128 + wm + mi * 16 + g;
        const int r1 = r0 + 8;
        const float b0 = bias[r0], b1 = bias[r1];
        const size_t base0 = ((size_t)img * 1024 + r0) * HW + spbase;
        const size_t base1 = ((size_t)img * 1024 + r1) * HW + spbase;
        #pragma unroll
        for (int n8 = 0; n8 < 8; n8++) {
            const int col = wn + n8 * 8 + tc * 2;
            const float2 x0 = *(const float2*)(resid + base0 + col);
            const float2 x1 = *(const float2*)(resid + base1 + col);
            float2 v0, v1;
            v0.x = fmaxf(acc[mi][n8][0] + b0 + x0.x, 0.f);
            v0.y = fmaxf(acc[mi][n8][1] + b0 + x0.y, 0.f);
            v1.x = fmaxf(acc[mi][n8][2] + b1 + x1.x, 0.f);
            v1.y = fmaxf(acc[mi][n8][3] + b1 + x1.y, 0.f);
            *(float2*)(C + base0 + col) = v0;
            *(float2*)(C + base1 + col) = v1;
        }
    }
}

// ---------------- launch ----------------
extern "C" void kernel_launch(void* const* d_in, const int* in_sizes, int n_in,
                              void* d_out, int out_size)
{
    const float* x  = (const float*)d_in[0];
    const float* w1 = (const float*)d_in[1];
    const float* w2 = (const float*)d_in[2];
    const float* w3 = (const float*)d_in[3];
    const float* s1 = (const float*)d_in[4];
    const float* b1 = (const float*)d_in[5];
    const float* s2 = (const float*)d_in[6];
    const float* b2 = (const float*)d_in[7];
    const float* s3 = (const float*)d_in[8];
    const float* b3 = (const float*)d_in[9];
    float* out = (float*)d_out;

    __half *o1, *o2, *w1h, *w2h, *w3h;
    cudaGetSymbolAddress((void**)&o1,  g_o1h);
    cudaGetSymbolAddress((void**)&o2,  g_o2h);
    cudaGetSymbolAddress((void**)&w1h, g_w1h);
    cudaGetSymbolAddress((void**)&w2h, g_w2h);
    cudaGetSymbolAddress((void**)&w3h, g_w3h);

    cudaFuncSetAttribute(btl1f, cudaFuncAttributeMaxDynamicSharedMemorySize, SMEM_C1);
    cudaFuncSetAttribute(btl2,  cudaFuncAttributeMaxDynamicSharedMemorySize, SMEM_BIG);
    cudaFuncSetAttribute(btl3,  cudaFuncAttributeMaxDynamicSharedMemorySize, SMEM_C3);

    prep_w <<<1024, 256>>>(w1, s1, w1h, 1024);
    prep_w2<<<2304, 256>>>(w2, s2, w2h);
    prep_w <<<1024, 256>>>(w3, s3, w3h, 256);

    // conv1: fused transpose + GEMM, M=256, K=1024, tile 128x256
    btl1f<<<dim3(4, 2, 32), 256, SMEM_C1>>>(w1h, x, o1, b1);
    // conv2: 3x3 implicit, K=9*256, tile 128x256
    btl2 <<<dim3(4, 2, 32), 256, SMEM_BIG>>>(w2h, o1, o2, b2);
    // conv3: M=1024, K=256, + residual, NCHW fp32 out
    btl3 <<<dim3(8, 8, 32), 256, SMEM_C3>>>(w3h, o2, out, b3, x);
}

// round 7
// speedup vs baseline: 2.2831x; 1.0015x over previous
#include <cuda_runtime.h>
#include <cuda_fp16.h>
#include <cstdint>

#define HW 1024
#define N_IMG 32
#define SMEM_C1 139264    // conv1: 4x16KB A + 2x32KB B (>= epilogue 8*64*68*4)
#define SMEM_BIG 196608   // conv2: 4 stages x (16KB A + 32KB B)
#define SMEM_C3  98304    // conv3: 3 stages x (16KB + 16KB)

// ---------------- device scratch ----------------
__device__ __half g_o1h[N_IMG * HW * 256];
__device__ __half g_o2h[N_IMG * HW * 256];
__device__ __half g_w1h[256 * 1024];
__device__ __half g_w2h[9 * 256 * 256];       // [off][co][ci]
__device__ __half g_w3h[1024 * 256];

__device__ __forceinline__ uint32_t smem_u32(const void* p) {
    uint32_t a;
    asm("{ .reg .u64 t; cvta.to.shared.u64 t, %1; cvt.u32.u64 %0, t; }" : "=r"(a) : "l"(p));
    return a;
}
__device__ __forceinline__ void cpasync(uint32_t s, const void* g, uint32_t srcsz) {
    asm volatile("cp.async.cg.shared.global [%0], [%1], 16, %2;"
                 :: "r"(s), "l"(g), "r"(srcsz) : "memory");
}
__device__ __forceinline__ void cpcommit() { asm volatile("cp.async.commit_group;" ::: "memory"); }
template<int N>
__device__ __forceinline__ void cpwait() { asm volatile("cp.async.wait_group %0;" :: "n"(N) : "memory"); }

__device__ __forceinline__ void ldsm4(uint32_t* r, uint32_t addr) {
    asm volatile("ldmatrix.sync.aligned.m8n8.x4.shared.b16 {%0,%1,%2,%3}, [%4];"
                 : "=r"(r[0]), "=r"(r[1]), "=r"(r[2]), "=r"(r[3]) : "r"(addr));
}
// fp16 accumulate (2x rate vs fp32 acc on the legacy pipe)
__device__ __forceinline__ void mma_h(uint32_t* d, const uint32_t* a, uint32_t b0, uint32_t b1) {
    asm volatile(
        "mma.sync.aligned.m16n8k16.row.col.f16.f16.f16.f16 "
        "{%0,%1}, {%2,%3,%4,%5}, {%6,%7}, {%0,%1};\n"
        : "+r"(d[0]), "+r"(d[1])
        : "r"(a[0]), "r"(a[1]), "r"(a[2]), "r"(a[3]), "r"(b0), "r"(b1));
}
// fp32 accumulate (conv3)
__device__ __forceinline__ void mma_f16(float* d, const uint32_t* a, uint32_t b0, uint32_t b1) {
    asm volatile(
        "mma.sync.aligned.m16n8k16.row.col.f32.f16.f16.f32 "
        "{%0,%1,%2,%3}, {%4,%5,%6,%7}, {%8,%9}, {%0,%1,%2,%3};\n"
        : "+f"(d[0]), "+f"(d[1]), "+f"(d[2]), "+f"(d[3])
        : "r"(a[0]), "r"(a[1]), "r"(a[2]), "r"(a[3]), "r"(b0), "r"(b1));
}

// ---------------- prep kernels ----------------
__global__ void prep_w(const float* __restrict__ w, const float* __restrict__ s,
                       __half* __restrict__ o, int K) {
    int i = blockIdx.x * 256 + threadIdx.x;
    o[i] = __float2half_rn(w[i] * s[i / K]);
}
__global__ void prep_w2(const float* __restrict__ w2, const float* __restrict__ s2,
                        __half* __restrict__ o) {
    int i = blockIdx.x * 256 + threadIdx.x;   // 9*256*256
    int off = i >> 16, rem = i & 65535;
    int co = rem >> 8, ci = rem & 255;
    o[i] = __float2half_rn(w2[co * 2304 + ci * 9 + off] * s2[co]);
}

// ---------------- epilogue: per-warp 64x64 staging -> ch-last fp16 ----------------
__device__ __forceinline__ void epilogue_chlast(
    char* smem, uint32_t hacc[4][8][2], __half* Cout, const float* bias,
    int img, int bm, int spbase, int wm, int wn, int w, int lane)
{
    float* stw = (float*)smem + w * (64 * 68);
    const int g = lane >> 2, tc = lane & 3;
    #pragma unroll
    for (int mi = 0; mi < 4; mi++) {
        const int rg = bm * 128 + wm + mi * 16 + g;
        const float b0 = bias[rg], b1 = bias[rg + 8];
        const int col = mi * 16 + g;
        #pragma unroll
        for (int n8 = 0; n8 < 8; n8++) {
            const int spl = n8 * 8 + tc * 2;
            const __half2 h0 = *(const __half2*)&hacc[mi][n8][0];  // row g
            const __half2 h1 = *(const __half2*)&hacc[mi][n8][1];  // row g+8
            stw[spl * 68 + col]           = fmaxf(__low2float(h0)  + b0, 0.f);
            stw[(spl + 1) * 68 + col]     = fmaxf(__high2float(h0) + b0, 0.f);
            stw[spl * 68 + col + 8]       = fmaxf(__low2float(h1)  + b1, 0.f);
            stw[(spl + 1) * 68 + col + 8] = fmaxf(__high2float(h1) + b1, 0.f);
        }
    }
    __syncwarp();
    const int co8 = (lane & 7) * 8, spr = lane >> 3;
    #pragma unroll
    for (int it = 0; it < 16; it++) {
        const int spl = spr + it * 4;
        const float* src = stw + spl * 68 + co8;
        __half2 h0 = __floats2half2_rn(src[0], src[1]);
        __half2 h1 = __floats2half2_rn(src[2], src[3]);
        __half2 h2 = __floats2half2_rn(src[4], src[5]);
        __half2 h3 = __floats2half2_rn(src[6], src[7]);
        __half* dst = Cout + ((size_t)img * HW + spbase + wn + spl) * 256
                           + bm * 128 + wm + co8;
        uint4 pk;
        pk.x = *(uint32_t*)&h0; pk.y = *(uint32_t*)&h1;
        pk.z = *(uint32_t*)&h2; pk.w = *(uint32_t*)&h3;
        *(uint4*)dst = pk;
    }
}

// ---------------- conv1: fused NCHW->ch-last transpose + GEMM (fp16 acc) ----------------
__global__ void __launch_bounds__(256, 1)
btl1f(const __half* __restrict__ A, const float* __restrict__ X,
      __half* __restrict__ Cout, const float* __restrict__ bias)
{
    extern __shared__ char smem[];
    const uint32_t sb = smem_u32(smem);
    const int tid = threadIdx.x;
    const int img = blockIdx.z, bm = blockIdx.y, bn = blockIdx.x;
    const int spbase = bn * 256;
    const float* Ximg = X + (size_t)img * 1024 * HW;

    const int irow = tid >> 1, ihalf = tid & 1;
    auto issueA = [&](int s) {
        const uint32_t bufA = sb + (s & 3) * 16384;
        const __half* gA = A + (size_t)(bm * 128 + irow) * 1024 + s * 64 + ihalf * 32;
        const int r7 = irow & 7;
        #pragma unroll
        for (int c = 0; c < 4; c++) {
            const int ch = ihalf * 4 + c;
            cpasync(bufA + irow * 128 + ((ch ^ r7) << 4), gA + c * 8, 16);
        }
        cpcommit();
    };

    uint32_t breg[8][4];
    auto ldB = [&](int s) {
        #pragma unroll
        for (int it = 0; it < 8; it++) {
            const int u = tid + it * 256;
            const int sp = u & 255, cig = u >> 8;
            const float* g = Ximg + (size_t)(s * 64 + cig * 8) * HW + spbase + sp;
            float v0 = g[0],      v1 = g[HW],     v2 = g[2 * HW], v3 = g[3 * HW];
            float v4 = g[4 * HW], v5 = g[5 * HW], v6 = g[6 * HW], v7 = g[7 * HW];
            __half2 h0 = __floats2half2_rn(v0, v1);
            __half2 h1 = __floats2half2_rn(v2, v3);
            __half2 h2 = __floats2half2_rn(v4, v5);
            __half2 h3 = __floats2half2_rn(v6, v7);
            breg[it][0] = *(uint32_t*)&h0; breg[it][1] = *(uint32_t*)&h1;
            breg[it][2] = *(uint32_t*)&h2; breg[it][3] = *(uint32_t*)&h3;
        }
    };
    auto stsB = [&](int s) {
        char* bufB = smem + 65536 + (s & 1) * 32768;
        #pragma unroll
        for (int it = 0; it < 8; it++) {
            const int u = tid + it * 256;
            const int sp = u & 255, cig = u >> 8;
            uint4 pk;
            pk.x = breg[it][0]; pk.y = breg[it][1];
            pk.z = breg[it][2]; pk.w = breg[it][3];
            *(uint4*)(bufB + sp * 128 + ((cig ^ (sp & 7)) << 4)) = pk;
        }
    };

    const int lane = tid & 31, w = tid >> 5;
    const int wm = (w & 1) * 64, wn = (w >> 1) * 64;
    const int l7 = lane & 7;
    const int rAl = lane & 15, cA = lane >> 4;
    const int rBl = ((lane >> 4) << 3) + l7, cB = (lane >> 3) & 1;

    uint32_t hacc[4][8][2];
    #pragma unroll
    for (int i = 0; i < 4; i++)
        #pragma unroll
        for (int j = 0; j < 8; j++) { hacc[i][j][0] = 0u; hacc[i][j][1] = 0u; }

    ldB(0); stsB(0);
    issueA(0); issueA(1); issueA(2);

    const int NS = 16;
    for (int s = 0; s < NS; s++) {
        cpwait<2>();
        __syncthreads();
        if (s + 1 < NS) ldB(s + 1);

        const uint32_t bufA = sb + (s & 3) * 16384;
        const uint32_t bufB = sb + 65536 + (s & 1) * 32768;
        #pragma unroll
        for (int kq = 0; kq < 4; kq++) {
            uint32_t a[4][4], b[4][4];
            #pragma unroll
            for (int mi = 0; mi < 4; mi++) {
                const int row = wm + mi * 16 + rAl;
                ldsm4(a[mi], bufA + row * 128 + (((2 * kq + cA) ^ l7) << 4));
            }
            #pragma unroll
            for (int np = 0; np < 4; np++) {
                const int row = wn + np * 16 + rBl;
                ldsm4(b[np], bufB + row * 128 + (((2 * kq + cB) ^ l7) << 4));
            }
            #pragma unroll
            for (int mi = 0; mi < 4; mi++)
                #pragma unroll
                for (int np = 0; np < 4; np++) {
                    mma_h(hacc[mi][np * 2 + 0], a[mi], b[np][0], b[np][1]);
                    mma_h(hacc[mi][np * 2 + 1], a[mi], b[np][2], b[np][3]);
                }
        }
        if (s + 3 < NS) issueA(s + 3); else cpcommit();
        if (s + 1 < NS) stsB(s + 1);
    }

    __syncthreads();
    epilogue_chlast(smem, hacc, Cout, bias, img, bm, spbase, wm, wn, w, lane);
}

// ---------------- conv2: implicit 3x3, big tile (fp16 acc) ----------------
__global__ void __launch_bounds__(256, 1)
btl2(const __half* __restrict__ A, const __half* __restrict__ Bt,
     __half* __restrict__ Cout, const float* __restrict__ bias)
{
    extern __shared__ char smem[];
    const uint32_t sb = smem_u32(smem);
    const int tid = threadIdx.x;
    const int img = blockIdx.z, bm = blockIdx.y, bn = blockIdx.x;
    const int spbase = bn * 256;
    const __half* Bimg = Bt + (size_t)img * HW * 256;

    const int irow = tid >> 1, ihalf = tid & 1;
    auto issue = [&](int s) {
        const uint32_t bufA = sb + (s & 3) * 49152;
        const uint32_t bufB = bufA + 16384;
        const int off = s >> 2, ci0 = (s & 3) * 64;
        const __half* gA = A + off * 65536 + (bm * 128 + irow) * 256 + ci0 + ihalf * 32;
        const int dh = off / 3 - 1, dw = off % 3 - 1;
        const __half *gB0, *gB1;
        uint32_t bsz0, bsz1;
        {
            const int sp = spbase + irow;
            const int hh = (sp >> 5) + dh, ww = (sp & 31) + dw;
            const bool v = ((unsigned)hh < 32u) & ((unsigned)ww < 32u);
            gB0 = v ? Bimg + (size_t)((hh << 5) + ww) * 256 + ci0 + ihalf * 32 : Bimg;
            bsz0 = v ? 16 : 0;
        }
        {
            const int sp = spbase + irow + 128;
            const int hh = (sp >> 5) + dh, ww = (sp & 31) + dw;
            const bool v = ((unsigned)hh < 32u) & ((unsigned)ww < 32u);
            gB1 = v ? Bimg + (size_t)((hh << 5) + ww) * 256 + ci0 + ihalf * 32 : Bimg;
            bsz1 = v ? 16 : 0;
        }
        const int r7 = irow & 7;
        #pragma unroll
        for (int c = 0; c < 4; c++) {
            const int ch = ihalf * 4 + c;
            const uint32_t so = irow * 128 + ((ch ^ r7) << 4);
            cpasync(bufA + so,         gA  + c * 8, 16);
            cpasync(bufB + so,         gB0 + c * 8, bsz0);
            cpasync(bufB + 16384 + so, gB1 + c * 8, bsz1);
        }
        cpcommit();
    };

    const int lane = tid & 31, w = tid >> 5;
    const int wm = (w & 1) * 64, wn = (w >> 1) * 64;
    const int l7 = lane & 7;
    const int rAl = lane & 15, cA = lane >> 4;
    const int rBl = ((lane >> 4) << 3) + l7, cB = (lane >> 3) & 1;

    uint32_t hacc[4][8][2];
    #pragma unroll
    for (int i = 0; i < 4; i++)
        #pragma unroll
        for (int j = 0; j < 8; j++) { hacc[i][j][0] = 0u; hacc[i][j][1] = 0u; }

    issue(0); issue(1); issue(2);

    const int NS = 36;
    for (int s = 0; s < NS; s++) {
        if (s + 2 < NS) cpwait<2>();
        else if (s + 1 < NS) cpwait<1>();
        else cpwait<0>();
        __syncthreads();
        if (s + 3 < NS) issue(s + 3);

        const uint32_t bufA = sb + (s & 3) * 49152;
        const uint32_t bufB = bufA + 16384;
        #pragma unroll
        for (int kq = 0; kq < 4; kq++) {
            uint32_t a[4][4], b[4][4];
            #pragma unroll
            for (int mi = 0; mi < 4; mi++) {
                const int row = wm + mi * 16 + rAl;
                ldsm4(a[mi], bufA + row * 128 + (((2 * kq + cA) ^ l7) << 4));
            }
            #pragma unroll
            for (int np = 0; np < 4; np++) {
                const int row = wn + np * 16 + rBl;
                ldsm4(b[np], bufB + row * 128 + (((2 * kq + cB) ^ l7) << 4));
            }
            #pragma unroll
            for (int mi = 0; mi < 4; mi++)
                #pragma unroll
                for (int np = 0; np < 4; np++) {
                    mma_h(hacc[mi][np * 2 + 0], a[mi], b[np][0], b[np][1]);
                    mma_h(hacc[mi][np * 2 + 1], a[mi], b[np][2], b[np][3]);
                }
        }
    }

    __syncthreads();
    epilogue_chlast(smem, hacc, Cout, bias, img, bm, spbase, wm, wn, w, lane);
}

// ---------------- conv3: fp32 acc, residual, NCHW fp32 out (unchanged) ----------------
__global__ void __launch_bounds__(256, 2)
btl3(const __half* __restrict__ A, const __half* __restrict__ Bt,
     float* __restrict__ C, const float* __restrict__ bias,
     const float* __restrict__ resid)
{
    extern __shared__ char smem[];
    const uint32_t sb = smem_u32(smem);
    const int tid = threadIdx.x;
    const int img = blockIdx.z, bm = blockIdx.y, bn = blockIdx.x;
    const int spbase = bn * 128;
    const __half* Bimg = Bt + (size_t)img * HW * 256;

    const int irow = tid >> 1, ihalf = tid & 1;
    auto issue = [&](int s) {
        const uint32_t bufA = sb + (s % 3) * 32768;
        const uint32_t bufB = bufA + 16384;
        const int k0 = s * 64;
        const __half* gA = A + (size_t)(bm * 128 + irow) * 256 + k0 + ihalf * 32;
        const __half* gB = Bimg + (size_t)(spbase + irow) * 256 + k0 + ihalf * 32;
        const int r7 = irow & 7;
        #pragma unroll
        for (int c = 0; c < 4; c++) {
            const int ch = ihalf * 4 + c;
            const uint32_t so = irow * 128 + ((ch ^ r7) << 4);
            cpasync(bufA + so, gA + c * 8, 16);
            cpasync(bufB + so, gB + c * 8, 16);
        }
        cpcommit();
    };

    const int lane = tid & 31, w = tid >> 5;
    const int wm = (w & 3) << 5, wn = (w >> 2) << 6;
    const int l7 = lane & 7;
    const int rAl = lane & 15, cA = lane >> 4;
    const int rBl = ((lane >> 4) << 3) + l7, cB = (lane >> 3) & 1;

    float acc[2][8][4];
    #pragma unroll
    for (int i = 0; i < 2; i++)
        #pragma unroll
        for (int j = 0; j < 8; j++)
            #pragma unroll
            for (int q = 0; q < 4; q++) acc[i][j][q] = 0.f;

    issue(0); issue(1);
    const int NS = 4;
    for (int s = 0; s < NS; s++) {
        if (s + 2 < NS) { issue(s + 2); cpwait<2>(); }
        else if (s + 1 < NS) cpwait<1>();
        else cpwait<0>();
        __syncthreads();

        const uint32_t bufA = sb + (s % 3) * 32768;
        const uint32_t bufB = bufA + 16384;
        #pragma unroll
        for (int kq = 0; kq < 4; kq++) {
            uint32_t a[2][4], b[4][4];
            #pragma unroll
            for (int mi = 0; mi < 2; mi++) {
                const int row = wm + mi * 16 + rAl;
                ldsm4(a[mi], bufA + row * 128 + (((2 * kq + cA) ^ l7) << 4));
            }
            #pragma unroll
            for (int np = 0; np < 4; np++) {
                const int row = wn + np * 16 + rBl;
                ldsm4(b[np], bufB + row * 128 + (((2 * kq + cB) ^ l7) << 4));
            }
            #pragma unroll
            for (int mi = 0; mi < 2; mi++)
                #pragma unroll
                for (int np = 0; np < 4; np++) {
                    mma_f16(acc[mi][np * 2 + 0], a[mi], b[np][0], b[np][1]);
                    mma_f16(acc[mi][np * 2 + 1], a[mi], b[np][2], b[np][3]);
                }
        }
        __syncthreads();
    }

    const int g = lane >> 2, tc = lane & 3;
    #pragma unroll
    for (int mi = 0; mi < 2; mi++) {
        const int r0 = bm * 128 + wm + mi * 16 + g;
        const int r1 = r0 + 8;
        const float b0 = bias[r0], b1 = bias[r1];
        const size_t base0 = ((size_t)img * 1024 + r0) * HW + spbase;
        const size_t base1 = ((size_t)img * 1024 + r1) * HW + spbase;
        #pragma unroll
        for (int n8 = 0; n8 < 8; n8++) {
            const int col = wn + n8 * 8 + tc * 2;
            const float2 x0 = *(const float2*)(resid + base0 + col);
            const float2 x1 = *(const float2*)(resid + base1 + col);
            float2 v0, v1;
            v0.x = fmaxf(acc[mi][n8][0] + b0 + x0.x, 0.f);
            v0.y = fmaxf(acc[mi][n8][1] + b0 + x0.y, 0.f);
            v1.x = fmaxf(acc[mi][n8][2] + b1 + x1.x, 0.f);
            v1.y = fmaxf(acc[mi][n8][3] + b1 + x1.y, 0.f);
            *(float2*)(C + base0 + col) = v0;
            *(float2*)(C + base1 + col) = v1;
        }
    }
}

// ---------------- launch ----------------
extern "C" void kernel_launch(void* const* d_in, const int* in_sizes, int n_in,
                              void* d_out, int out_size)
{
    const float* x  = (const float*)d_in[0];
    const float* w1 = (const float*)d_in[1];
    const float* w2 = (const float*)d_in[2];
    const float* w3 = (const float*)d_in[3];
    const float* s1 = (const float*)d_in[4];
    const float* b1 = (const float*)d_in[5];
    const float* s2 = (const float*)d_in[6];
    const float* b2 = (const float*)d_in[7];
    const float* s3 = (const float*)d_in[8];
    const float* b3 = (const float*)d_in[9];
    float* out = (float*)d_out;

    __half *o1, *o2, *w1h, *w2h, *w3h;
    cudaGetSymbolAddress((void**)&o1,  g_o1h);
    cudaGetSymbolAddress((void**)&o2,  g_o2h);
    cudaGetSymbolAddress((void**)&w1h, g_w1h);
    cudaGetSymbolAddress((void**)&w2h, g_w2h);
    cudaGetSymbolAddress((void**)&w3h, g_w3h);

    cudaFuncSetAttribute(btl1f, cudaFuncAttributeMaxDynamicSharedMemorySize, SMEM_C1);
    cudaFuncSetAttribute(btl2,  cudaFuncAttributeMaxDynamicSharedMemorySize, SMEM_BIG);
    cudaFuncSetAttribute(btl3,  cudaFuncAttributeMaxDynamicSharedMemorySize, SMEM_C3);

    prep_w <<<1024, 256>>>(w1, s1, w1h, 1024);
    prep_w2<<<2304, 256>>>(w2, s2, w2h);
    prep_w <<<1024, 256>>>(w3, s3, w3h, 256);

    // conv1: fused transpose + GEMM, M=256, K=1024, tile 128x256, fp16 acc
    btl1f<<<dim3(4, 2, 32), 256, SMEM_C1>>>(w1h, x, o1, b1);
    // conv2: 3x3 implicit, K=9*256, tile 128x256, fp16 acc
    btl2 <<<dim3(4, 2, 32), 256, SMEM_BIG>>>(w2h, o1, o2, b2);
    // conv3: M=1024, K=256, + residual, fp32 acc, NCHW out
    btl3 <<<dim3(8, 8, 32), 256, SMEM_C3>>>(w3h, o2, out, b3, x);
}